// round 16
// baseline (speedup 1.0000x reference)
#include <cuda_runtime.h>
#include <cuda_fp16.h>
#include <cstdint>
#include <math.h>

#define NTOK 1024
#define DIM  512
#define NHEAD 8
#define EXP  256
#define NE   65536
#define KSEL 16

// ======================= device scratch ======================================
__device__ float g_qh[NTOK * NHEAD * 128];
__device__ float g_s1[NTOK * NHEAD * EXP];
__device__ float g_s2[NTOK * NHEAD * EXP];
__device__ float g_P[NE];
__device__ __align__(128) __half g_Qh[NTOK * DIM];
__device__ __align__(128) __half g_Wdh[(size_t)NE * DIM];    // 64 MB fp16
__device__ __align__(128) __half g_WuTh[(size_t)DIM * NE];   // 64 MB fp16 (P-folded)
__device__ __align__(128) __half g_Sh[(size_t)NTOK * NE];    // 128 MB fp16

// ======================= small helpers =======================================
__device__ __forceinline__ void mma16816(float c[4], const uint32_t a[4],
                                         uint32_t b0, uint32_t b1) {
  asm volatile(
      "mma.sync.aligned.m16n8k16.row.col.f32.f16.f16.f32 "
      "{%0,%1,%2,%3}, {%4,%5,%6,%7}, {%8,%9}, {%0,%1,%2,%3};"
      : "+f"(c[0]), "+f"(c[1]), "+f"(c[2]), "+f"(c[3])
      : "r"(a[0]), "r"(a[1]), "r"(a[2]), "r"(a[3]), "r"(b0), "r"(b1));
}
__device__ __forceinline__ void ldsm4(uint32_t r[4], uint32_t addr) {
  asm volatile("ldmatrix.sync.aligned.m8n8.x4.shared.b16 {%0,%1,%2,%3}, [%4];"
               : "=r"(r[0]), "=r"(r[1]), "=r"(r[2]), "=r"(r[3]) : "r"(addr));
}
__device__ __forceinline__ void cp16(uint32_t dst, const void* src) {
  asm volatile("cp.async.cg.shared.global [%0], [%1], 16;" :: "r"(dst), "l"(src));
}
#define CP_COMMIT asm volatile("cp.async.commit_group;" ::: "memory")
#define CP_WAIT1  asm volatile("cp.async.wait_group 1;" ::: "memory")
#define CP_WAIT0  asm volatile("cp.async.wait_group 0;" ::: "memory")

__device__ __forceinline__ uint32_t pack2h(float x0, float x1) {
  return (uint32_t)__half_as_ushort(__float2half(x0)) |
         ((uint32_t)__half_as_ushort(__float2half(x1)) << 16);
}

// ======================= fused prep kernel (no wu work) =======================
#define PB_QH    256
#define PB_ZERO  1024
#define PB_WD    16384
#define PREP_BLOCKS (PB_QH + PB_ZERO + PB_WD)

__device__ void gemm_qh_body(const float* __restrict__ A,
                             const float* __restrict__ B,
                             const float* __restrict__ bias,
                             int bid, char* buf) {
  float (*As)[64] = (float(*)[64])buf;
  float (*Bs)[64] = (float(*)[64])(buf + 4096);
  int m0 = (bid & 15) * 64, n0 = (bid >> 4) * 64;
  int tid = threadIdx.x;
  int tx = tid & 15, ty = tid >> 4;
  int lr = tid >> 2, lc = tid & 3;
  float acc[4][4];
#pragma unroll
  for (int i = 0; i < 4; i++)
#pragma unroll
    for (int j = 0; j < 4; j++) acc[i][j] = 0.f;
  for (int k0 = 0; k0 < 512; k0 += 16) {
    float4 va = *(const float4*)&A[(size_t)(m0 + lr) * 512 + k0 + lc * 4];
    As[lc * 4 + 0][lr] = va.x; As[lc * 4 + 1][lr] = va.y;
    As[lc * 4 + 2][lr] = va.z; As[lc * 4 + 3][lr] = va.w;
    float4 vb = *(const float4*)&B[(size_t)(n0 + lr) * 512 + k0 + lc * 4];
    Bs[lc * 4 + 0][lr] = vb.x; Bs[lc * 4 + 1][lr] = vb.y;
    Bs[lc * 4 + 2][lr] = vb.z; Bs[lc * 4 + 3][lr] = vb.w;
    __syncthreads();
#pragma unroll
    for (int k = 0; k < 16; k++) {
      float a[4], b[4];
      *(float4*)&a[0] = *(const float4*)&As[k][ty * 4];
      *(float4*)&b[0] = *(const float4*)&Bs[k][tx * 4];
#pragma unroll
      for (int i = 0; i < 4; i++)
#pragma unroll
        for (int j = 0; j < 4; j++) acc[i][j] += a[i] * b[j];
    }
    __syncthreads();
  }
#pragma unroll
  for (int i = 0; i < 4; i++) {
    int m = m0 + ty * 4 + i;
#pragma unroll
    for (int j = 0; j < 4; j++) {
      int n = n0 + tx * 4 + j;
      g_qh[(size_t)m * 1024 + n] = acc[i][j] + bias[n];
    }
  }
}

__device__ void zero_convq_body(float* __restrict__ out,
                                const float* __restrict__ qsrc, int bid) {
  int i = bid * 256 + threadIdx.x;
  int stride = PB_ZERO * 256;
  for (int j = i; j < NE; j += stride) g_P[j] = 0.f;
  for (int j = i; j < NTOK * DIM; j += stride) out[j] = 0.f;
  for (int j = i; j < NTOK * DIM / 8; j += stride) {
    const float4* s = (const float4*)qsrc + (size_t)j * 2;
    float4 a = s[0], b = s[1];
    ((uint4*)g_Qh)[j] = make_uint4(pack2h(a.x, a.y), pack2h(a.z, a.w),
                                   pack2h(b.x, b.y), pack2h(b.z, b.w));
  }
}

__device__ void conv_wd_body(const float* __restrict__ src, int bid) {
  int i = bid * 256 + threadIdx.x;
  const float4* s = (const float4*)src + (size_t)i * 2;
  float4 a = s[0], b = s[1];
  ((uint4*)g_Wdh)[i] = make_uint4(pack2h(a.x, a.y), pack2h(a.z, a.w),
                                  pack2h(b.x, b.y), pack2h(b.z, b.w));
}

__global__ __launch_bounds__(256) void prep_kernel(
    float* __restrict__ out, const float* __restrict__ queries,
    const float* __restrict__ Wq, const float* __restrict__ bq,
    const float* __restrict__ w_down) {
  __shared__ __align__(16) char buf[8192];
  int b = blockIdx.x;
  if (b < PB_QH) {
    gemm_qh_body(queries, Wq, bq, b, buf);
  } else if (b < PB_QH + PB_ZERO) {
    zero_convq_body(out, queries, b - PB_QH);
  } else {
    conv_wd_body(w_down, b - (PB_QH + PB_ZERO));
  }
}

// ======================= scores as tiled GEMM =================================
__global__ __launch_bounds__(256) void scores_gemm_kernel(
    const float* __restrict__ keys) {
  __shared__ float As[16][64];
  __shared__ float Bs[16][64];
  int m0 = blockIdx.x * 64;
  int e0 = blockIdx.y * 64;
  int hh = blockIdx.z;
  int h = hh >> 1, half = hh & 1;
  const float* A = g_qh + h * 128 + half * 64;
  const float* B = keys + ((size_t)hh * 256 + e0) * 64;
  float* dst = (half == 0) ? g_s1 : g_s2;

  int tid = threadIdx.x;
  int tx = tid & 15, ty = tid >> 4;
  int lr = tid >> 2, lc = tid & 3;
  float acc[4][4];
#pragma unroll
  for (int i = 0; i < 4; i++)
#pragma unroll
    for (int j = 0; j < 4; j++) acc[i][j] = 0.f;

#pragma unroll
  for (int k0 = 0; k0 < 64; k0 += 16) {
    float4 va = *(const float4*)&A[(size_t)(m0 + lr) * 1024 + k0 + lc * 4];
    As[lc * 4 + 0][lr] = va.x; As[lc * 4 + 1][lr] = va.y;
    As[lc * 4 + 2][lr] = va.z; As[lc * 4 + 3][lr] = va.w;
    float4 vb = *(const float4*)&B[(size_t)lr * 64 + k0 + lc * 4];
    Bs[lc * 4 + 0][lr] = vb.x; Bs[lc * 4 + 1][lr] = vb.y;
    Bs[lc * 4 + 2][lr] = vb.z; Bs[lc * 4 + 3][lr] = vb.w;
    __syncthreads();
#pragma unroll
    for (int k = 0; k < 16; k++) {
      float a[4], b[4];
      *(float4*)&a[0] = *(const float4*)&As[k][ty * 4];
      *(float4*)&b[0] = *(const float4*)&Bs[k][tx * 4];
#pragma unroll
      for (int i = 0; i < 4; i++)
#pragma unroll
        for (int j = 0; j < 4; j++) acc[i][j] += a[i] * b[j];
    }
    __syncthreads();
  }
#pragma unroll
  for (int i = 0; i < 4; i++) {
    int nt = m0 + ty * 4 + i;
#pragma unroll
    for (int j = 0; j < 4; j++) {
      int e = e0 + tx * 4 + j;
      dst[((size_t)nt * NHEAD + h) * EXP + e] = acc[i][j];
    }
  }
}

// ======================= warp-level top-k ====================================
__device__ __forceinline__ void warp_top16(float v[8], int lid, float& mv, int& mi) {
  for (int k = 0; k < KSEL; k++) {
    float bv = v[0];
    int br = 0;
#pragma unroll
    for (int r = 1; r < 8; r++)
      if (v[r] > bv) { bv = v[r]; br = r; }
    int code = br * 32 + lid;
#pragma unroll
    for (int off = 16; off; off >>= 1) {
      float ov = __shfl_xor_sync(0xffffffffu, bv, off);
      int oc = __shfl_xor_sync(0xffffffffu, code, off);
      if (ov > bv || (ov == bv && oc < code)) { bv = ov; code = oc; }
    }
    if (lid == k) { mv = bv; mi = code; }
    int owner = code & 31, reg = code >> 5;
    if (lid == owner) {
#pragma unroll
      for (int r = 0; r < 8; r++)
        if (r == reg) v[r] = -INFINITY;
    }
  }
}

__global__ __launch_bounds__(256) void topk_kernel() {
  int lid = threadIdx.x & 31;
  int w = threadIdx.x >> 5;
  int row = blockIdx.x * 8 + w;
  float v[8];
  float m1v = 0.f, m2v = 0.f, m3v = 0.f;
  int m1i = 0, m2i = 0, m3i = 0;

  const float* s1 = g_s1 + (size_t)row * EXP;
#pragma unroll
  for (int r = 0; r < 8; r++) v[r] = s1[r * 32 + lid];
  warp_top16(v, lid, m1v, m1i);

  const float* s2 = g_s2 + (size_t)row * EXP;
#pragma unroll
  for (int r = 0; r < 8; r++) v[r] = s2[r * 32 + lid];
  warp_top16(v, lid, m2v, m2i);

#pragma unroll
  for (int r = 0; r < 8; r++) {
    int t = r * 32 + lid;
    float a = __shfl_sync(0xffffffffu, m1v, t >> 4);
    float b = __shfl_sync(0xffffffffu, m2v, t & 15);
    v[r] = a + b;
  }
  warp_top16(v, lid, m3v, m3i);

  float mx = __shfl_sync(0xffffffffu, m3v, 0);
  float p = (lid < 16) ? expf(m3v - mx) : 0.f;
  float sum = p;
#pragma unroll
  for (int off = 16; off; off >>= 1) sum += __shfl_xor_sync(0xffffffffu, sum, off);
  float inv = 1.0f / sum;
  int i1 = __shfl_sync(0xffffffffu, m1i, (m3i >> 4) & 15);
  int i2 = __shfl_sync(0xffffffffu, m2i, m3i & 15);
  if (lid < 16) atomicAdd(&g_P[i1 * EXP + i2], p * inv);
}

// ======================= HMMA mainloop (r13 config: 256 thr, 2m x 4n) =========
#define BM 128
#define BN 128
#define SM_A 0
#define SM_B 16384
#define STAGE_BYTES 32768
#define NSTAGE 3
#define DSMEM_SZ (NSTAGE * STAGE_BYTES)

__device__ __forceinline__ uint32_t swz128(int row, int seg) {
  return (uint32_t)(row * 128 + ((seg ^ (row & 7)) << 4));
}

__device__ __forceinline__ void issue_chunk(
    uint32_t smb, int stage, const char* A, const char* B,
    size_t sA, size_t sB, int ck, int tid) {
  uint32_t base = smb + stage * STAGE_BYTES;
  size_t ko = (size_t)ck * 128;
#pragma unroll
  for (int t = 0; t < 4; t++) {
    int q = tid + t * 256;
    int row = q >> 3, seg = q & 7;
    cp16(base + SM_A + swz128(row, seg), A + (size_t)row * sA + ko + seg * 16);
  }
#pragma unroll
  for (int t = 0; t < 4; t++) {
    int q = tid + t * 256;
    int row = q >> 3, seg = q & 7;
    cp16(base + SM_B + swz128(row, seg), B + (size_t)row * sB + ko + seg * 16);
  }
  CP_COMMIT;
}

__device__ __forceinline__ void mainloop1(
    const char* A, const char* B, size_t sA, size_t sB, int NC,
    float acc[4][4][4], char* sm) {
  uint32_t smb = (uint32_t)__cvta_generic_to_shared(sm);
  int tid = threadIdx.x, lane = tid & 31, wid = tid >> 5;
  int wm = (wid & 1) * 64, wn = (wid >> 1) * 32;
  int arow = ((lane >> 3) & 1) * 8 + (lane & 7);
  int aseg = lane >> 4;

  issue_chunk(smb, 0, A, B, sA, sB, 0, tid);
  issue_chunk(smb, 1, A, B, sA, sB, 1, tid);

  for (int ck = 0; ck < NC; ck++) {
    if (ck == NC - 1) { CP_WAIT0; } else { CP_WAIT1; }
    __syncthreads();
    if (ck + 2 < NC)
      issue_chunk(smb, (ck + 2) % NSTAGE, A, B, sA, sB, ck + 2, tid);
    uint32_t base = smb + (ck % NSTAGE) * STAGE_BYTES;
#pragma unroll
    for (int s = 0; s < 4; s++) {
      int seg = s * 2 + aseg;
      uint32_t Af[4][4], Bf[2][4];
#pragma unroll
      for (int g = 0; g < 2; g++) {
        int row = wn + g * 16 + arow;
        ldsm4(Bf[g], base + SM_B + swz128(row, seg));
      }
#pragma unroll
      for (int mt = 0; mt < 4; mt++) {
        int row = wm + mt * 16 + arow;
        ldsm4(Af[mt], base + SM_A + swz128(row, seg));
      }
#pragma unroll
      for (int mt = 0; mt < 4; mt++)
#pragma unroll
        for (int nt = 0; nt < 4; nt++) {
          int g = nt >> 1, j = nt & 1;
          mma16816(acc[mt][nt], Af[mt], Bf[g][j], Bf[g][j + 2]);
        }
    }
  }
}

// ---------- D1 fused: [0, 512) = trans_wu' blocks (WuT' = P-folded Wu^T);
//                      [512, 4608) = Sh = relu(Qh @ Wdh^T) tiles --------------
#define TRANS_BLOCKS 512
#define TILES_PER_TRANS 32    // 16384 tiles / 512 blocks

__device__ void trans_wu_p_body(const float* __restrict__ W, int blk, char* buf) {
  float (*t)[33] = (float(*)[33])buf;    // 64 x 33 floats = 8448 B
  int tid = threadIdx.x;
  int tx = tid & 31, ty = tid >> 5;      // 32 x 8
  for (int it = 0; it < TILES_PER_TRANS; it++) {
    int idx = blk * TILES_PER_TRANS + it;
    int kt = idx & 1023, nt = idx >> 10;
    int k0 = kt * 64, n0 = nt * 32;
#pragma unroll
    for (int i = 0; i < 8; i++) {
      int k = ty + 8 * i;
      t[k][tx] = W[(size_t)(k0 + k) * 512 + n0 + tx];
    }
    __syncthreads();
    float p0 = g_P[k0 + 2 * tx];
    float p1 = g_P[k0 + 2 * tx + 1];
#pragma unroll
    for (int q = 0; q < 4; q++) {
      int r = ty * 4 + q;
      float v0 = t[2 * tx][r] * p0;
      float v1 = t[2 * tx + 1][r] * p1;
      *(uint32_t*)&g_WuTh[(size_t)(n0 + r) * NE + k0 + 2 * tx] = pack2h(v0, v1);
    }
    __syncthreads();
  }
}

__global__ __launch_bounds__(256, 2) void d1_kernel(const float* __restrict__ w_up) {
  extern __shared__ __align__(1024) char dynsm[];
  if (blockIdx.x < TRANS_BLOCKS) {
    trans_wu_p_body(w_up, blockIdx.x, dynsm);
    return;
  }
  int bid = blockIdx.x - TRANS_BLOCKS;
  int m0 = (bid & 7) * BM, n0 = (bid >> 3) * BN;
  float acc[4][4][4];
#pragma unroll
  for (int a = 0; a < 4; a++)
#pragma unroll
    for (int c = 0; c < 4; c++)
#pragma unroll
      for (int d = 0; d < 4; d++) acc[a][c][d] = 0.f;

  mainloop1((const char*)(g_Qh + (size_t)m0 * 512),
            (const char*)(g_Wdh + (size_t)n0 * 512),
            1024, 1024, 8, acc, dynsm);

  int lane = threadIdx.x & 31, wid = threadIdx.x >> 5;
  int wm = (wid & 1) * 64, wn = (wid >> 1) * 32;
  int r0 = lane >> 2, cc = (lane & 3) * 2;
#pragma unroll
  for (int nt = 0; nt < 4; nt++) {
    int n = n0 + wn + nt * 8 + cc;
#pragma unroll
    for (int mt = 0; mt < 4; mt++) {
#pragma unroll
      for (int h = 0; h < 2; h++) {
        int m = m0 + wm + mt * 16 + r0 + h * 8;
        float v0 = fmaxf(acc[mt][nt][2 * h + 0], 0.f);
        float v1 = fmaxf(acc[mt][nt][2 * h + 1], 0.f);
        *(uint32_t*)&g_Sh[(size_t)m * NE + n] = pack2h(v0, v1);
      }
    }
  }
}

// ---------- D2: out += Sh @ WuT'^T ; M=1024, N=512, K=65536, splitK=9 --------
__global__ __launch_bounds__(256, 2) void d2_kernel(float* __restrict__ out) {
  extern __shared__ __align__(1024) char dynsm[];
  int m0 = blockIdx.x * BM;
  int n0 = blockIdx.y * BN;
  int z = blockIdx.z;
  int start = z * 113 + (z < 7 ? z : 7);
  int cnt = 113 + (z < 7 ? 1 : 0);
  size_t kb = (size_t)start * 128;
  float acc[4][4][4];
#pragma unroll
  for (int a = 0; a < 4; a++)
#pragma unroll
    for (int c = 0; c < 4; c++)
#pragma unroll
      for (int d = 0; d < 4; d++) acc[a][c][d] = 0.f;

  mainloop1((const char*)g_Sh + (size_t)m0 * 131072 + kb,
            (const char*)g_WuTh + (size_t)n0 * 131072 + kb,
            131072, 131072, cnt, acc, dynsm);

  int lane = threadIdx.x & 31, wid = threadIdx.x >> 5;
  int wm = (wid & 1) * 64, wn = (wid >> 1) * 32;
  int r0 = lane >> 2, cc = (lane & 3) * 2;
#pragma unroll
  for (int nt = 0; nt < 4; nt++) {
    int n = n0 + wn + nt * 8 + cc;
#pragma unroll
    for (int mt = 0; mt < 4; mt++) {
#pragma unroll
      for (int h = 0; h < 2; h++) {
        int m = m0 + wm + mt * 16 + r0 + h * 8;
        atomicAdd(&out[(size_t)m * DIM + n], acc[mt][nt][2 * h + 0]);
        atomicAdd(&out[(size_t)m * DIM + n + 1], acc[mt][nt][2 * h + 1]);
      }
    }
  }
}

// ======================= launch ==============================================
extern "C" void kernel_launch(void* const* d_in, const int* in_sizes, int n_in,
                              void* d_out, int out_size) {
  const float* queries = (const float*)d_in[0];
  const float* Wq      = (const float*)d_in[1];
  const float* bq      = (const float*)d_in[2];
  const float* keys    = (const float*)d_in[3];
  const float* w_down  = (const float*)d_in[4];
  const float* w_up    = (const float*)d_in[5];
  float* out = (float*)d_out;

  cudaFuncSetAttribute(d1_kernel, cudaFuncAttributeMaxDynamicSharedMemorySize, DSMEM_SZ);
  cudaFuncSetAttribute(d2_kernel, cudaFuncAttributeMaxDynamicSharedMemorySize, DSMEM_SZ);

  prep_kernel<<<PREP_BLOCKS, 256>>>(out, queries, Wq, bq, w_down);
  scores_gemm_kernel<<<dim3(16, 4, 16), 256>>>(keys);
  topk_kernel<<<1024, 256>>>();
  d1_kernel<<<TRANS_BLOCKS + 4096, 256, DSMEM_SZ>>>(w_up);
  d2_kernel<<<dim3(8, 4, 9), 256, DSMEM_SZ>>>(out);
}

// round 17
// speedup vs baseline: 1.0784x; 1.0784x over previous
#include <cuda_runtime.h>
#include <cuda_fp16.h>
#include <cstdint>
#include <math.h>

#define NTOK 1024
#define DIM  512
#define NHEAD 8
#define EXP  256
#define NE   65536
#define KSEL 16

// ======================= device scratch ======================================
__device__ float g_qh[NTOK * NHEAD * 128];
__device__ float g_s1[NTOK * NHEAD * EXP];
__device__ float g_s2[NTOK * NHEAD * EXP];
__device__ float g_P[NE];
__device__ __align__(128) __half g_Qh[NTOK * DIM];
__device__ __align__(128) __half g_Wdh[(size_t)NE * DIM];    // 64 MB fp16
__device__ __align__(128) __half g_WuTh[(size_t)DIM * NE];   // 64 MB fp16
__device__ __align__(128) __half g_Sh[(size_t)NTOK * NE];    // 128 MB fp16

// ======================= small helpers =======================================
__device__ __forceinline__ void mma16816(float c[4], const uint32_t a[4],
                                         uint32_t b0, uint32_t b1) {
  asm volatile(
      "mma.sync.aligned.m16n8k16.row.col.f32.f16.f16.f32 "
      "{%0,%1,%2,%3}, {%4,%5,%6,%7}, {%8,%9}, {%0,%1,%2,%3};"
      : "+f"(c[0]), "+f"(c[1]), "+f"(c[2]), "+f"(c[3])
      : "r"(a[0]), "r"(a[1]), "r"(a[2]), "r"(a[3]), "r"(b0), "r"(b1));
}
__device__ __forceinline__ void ldsm4(uint32_t r[4], uint32_t addr) {
  asm volatile("ldmatrix.sync.aligned.m8n8.x4.shared.b16 {%0,%1,%2,%3}, [%4];"
               : "=r"(r[0]), "=r"(r[1]), "=r"(r[2]), "=r"(r[3]) : "r"(addr));
}
__device__ __forceinline__ void cp16(uint32_t dst, const void* src) {
  asm volatile("cp.async.cg.shared.global [%0], [%1], 16;" :: "r"(dst), "l"(src));
}
#define CP_COMMIT asm volatile("cp.async.commit_group;" ::: "memory")
#define CP_WAIT1  asm volatile("cp.async.wait_group 1;" ::: "memory")
#define CP_WAIT0  asm volatile("cp.async.wait_group 0;" ::: "memory")

__device__ __forceinline__ uint32_t pack2h(float x0, float x1) {
  return (uint32_t)__half_as_ushort(__float2half(x0)) |
         ((uint32_t)__half_as_ushort(__float2half(x1)) << 16);
}

// ======================= fused prep kernel ====================================
// [0, 256)              gemm_qh 64x64 tiles
// [256, 1280)           zero P/out + conv Q
// [1280, 9472)          conv Wd (8192 blocks, 64B/thread, MLP 4)
// [9472, 25856)         transpose+convert Wu (read-coalesced block order)
#define PB_QH    256
#define PB_ZERO  1024
#define PB_WD    8192
#define PB_WU    16384
#define PREP_BLOCKS (PB_QH + PB_ZERO + PB_WD + PB_WU)

__device__ void gemm_qh_body(const float* __restrict__ A,
                             const float* __restrict__ B,
                             const float* __restrict__ bias,
                             int bid, char* buf) {
  float (*As)[64] = (float(*)[64])buf;
  float (*Bs)[64] = (float(*)[64])(buf + 4096);
  int m0 = (bid & 15) * 64, n0 = (bid >> 4) * 64;
  int tid = threadIdx.x;
  int tx = tid & 15, ty = tid >> 4;
  int lr = tid >> 2, lc = tid & 3;
  float acc[4][4];
#pragma unroll
  for (int i = 0; i < 4; i++)
#pragma unroll
    for (int j = 0; j < 4; j++) acc[i][j] = 0.f;
  for (int k0 = 0; k0 < 512; k0 += 16) {
    float4 va = *(const float4*)&A[(size_t)(m0 + lr) * 512 + k0 + lc * 4];
    As[lc * 4 + 0][lr] = va.x; As[lc * 4 + 1][lr] = va.y;
    As[lc * 4 + 2][lr] = va.z; As[lc * 4 + 3][lr] = va.w;
    float4 vb = *(const float4*)&B[(size_t)(n0 + lr) * 512 + k0 + lc * 4];
    Bs[lc * 4 + 0][lr] = vb.x; Bs[lc * 4 + 1][lr] = vb.y;
    Bs[lc * 4 + 2][lr] = vb.z; Bs[lc * 4 + 3][lr] = vb.w;
    __syncthreads();
#pragma unroll
    for (int k = 0; k < 16; k++) {
      float a[4], b[4];
      *(float4*)&a[0] = *(const float4*)&As[k][ty * 4];
      *(float4*)&b[0] = *(const float4*)&Bs[k][tx * 4];
#pragma unroll
      for (int i = 0; i < 4; i++)
#pragma unroll
        for (int j = 0; j < 4; j++) acc[i][j] += a[i] * b[j];
    }
    __syncthreads();
  }
#pragma unroll
  for (int i = 0; i < 4; i++) {
    int m = m0 + ty * 4 + i;
#pragma unroll
    for (int j = 0; j < 4; j++) {
      int n = n0 + tx * 4 + j;
      g_qh[(size_t)m * 1024 + n] = acc[i][j] + bias[n];
    }
  }
}

__device__ void zero_convq_body(float* __restrict__ out,
                                const float* __restrict__ qsrc, int bid) {
  int i = bid * 256 + threadIdx.x;
  int stride = PB_ZERO * 256;
  for (int j = i; j < NE; j += stride) g_P[j] = 0.f;
  for (int j = i; j < NTOK * DIM; j += stride) out[j] = 0.f;
  for (int j = i; j < NTOK * DIM / 8; j += stride) {
    const float4* s = (const float4*)qsrc + (size_t)j * 2;
    float4 a = s[0], b = s[1];
    ((uint4*)g_Qh)[j] = make_uint4(pack2h(a.x, a.y), pack2h(a.z, a.w),
                                   pack2h(b.x, b.y), pack2h(b.z, b.w));
  }
}

// 64B (16 floats) per thread: 4 independent LDG.128, 2 STG.128.
__device__ void conv_wd_body(const float* __restrict__ src, int bid) {
  int i = bid * 256 + threadIdx.x;          // 2M threads x 16 floats = 32M elems
  const float4* s = (const float4*)src + (size_t)i * 4;
  float4 a = s[0], b = s[1], c = s[2], d = s[3];
  ((uint4*)g_Wdh)[2 * i] = make_uint4(pack2h(a.x, a.y), pack2h(a.z, a.w),
                                      pack2h(b.x, b.y), pack2h(b.z, b.w));
  ((uint4*)g_Wdh)[2 * i + 1] = make_uint4(pack2h(c.x, c.y), pack2h(c.z, c.w),
                                          pack2h(d.x, d.y), pack2h(d.z, d.w));
}

// Wu [65536 x 512] fp32 -> WuT fp16 [512 x 65536]. Block order: 16 consecutive
// blocks share the same 64 k-rows (kt = b>>4), reading adjacent 128B pieces
// concurrently so L2 merges them into full-row streams.
__device__ void trans_wu_body(const float* __restrict__ W, int bid, char* buf) {
  float (*t)[33] = (float(*)[33])buf;
  int kt = bid >> 4, nt = bid & 15;
  int k0 = kt * 64, n0 = nt * 32;
  int tid = threadIdx.x;
  int tx = tid & 31, ty = tid >> 5;         // 32 x 8
#pragma unroll
  for (int i = 0; i < 8; i++) {
    int k = ty + 8 * i;
    t[k][tx] = W[(size_t)(k0 + k) * 512 + n0 + tx];
  }
  __syncthreads();
#pragma unroll
  for (int q = 0; q < 4; q++) {
    int r = ty * 4 + q;
    float v0 = t[2 * tx][r];
    float v1 = t[2 * tx + 1][r];
    *(uint32_t*)&g_WuTh[(size_t)(n0 + r) * NE + k0 + 2 * tx] = pack2h(v0, v1);
  }
}

__global__ __launch_bounds__(256) void prep_kernel(
    float* __restrict__ out, const float* __restrict__ queries,
    const float* __restrict__ Wq, const float* __restrict__ bq,
    const float* __restrict__ w_down, const float* __restrict__ w_up) {
  __shared__ __align__(16) char buf[8448];
  int b = blockIdx.x;
  if (b < PB_QH) {
    gemm_qh_body(queries, Wq, bq, b, buf);
  } else if (b < PB_QH + PB_ZERO) {
    zero_convq_body(out, queries, b - PB_QH);
  } else if (b < PB_QH + PB_ZERO + PB_WD) {
    conv_wd_body(w_down, b - (PB_QH + PB_ZERO));
  } else {
    trans_wu_body(w_up, b - (PB_QH + PB_ZERO + PB_WD), buf);
  }
}

// ======================= scores as tiled GEMM =================================
__global__ __launch_bounds__(256) void scores_gemm_kernel(
    const float* __restrict__ keys) {
  __shared__ float As[16][64];
  __shared__ float Bs[16][64];
  int m0 = blockIdx.x * 64;
  int e0 = blockIdx.y * 64;
  int hh = blockIdx.z;
  int h = hh >> 1, half = hh & 1;
  const float* A = g_qh + h * 128 + half * 64;
  const float* B = keys + ((size_t)hh * 256 + e0) * 64;
  float* dst = (half == 0) ? g_s1 : g_s2;

  int tid = threadIdx.x;
  int tx = tid & 15, ty = tid >> 4;
  int lr = tid >> 2, lc = tid & 3;
  float acc[4][4];
#pragma unroll
  for (int i = 0; i < 4; i++)
#pragma unroll
    for (int j = 0; j < 4; j++) acc[i][j] = 0.f;

#pragma unroll
  for (int k0 = 0; k0 < 64; k0 += 16) {
    float4 va = *(const float4*)&A[(size_t)(m0 + lr) * 1024 + k0 + lc * 4];
    As[lc * 4 + 0][lr] = va.x; As[lc * 4 + 1][lr] = va.y;
    As[lc * 4 + 2][lr] = va.z; As[lc * 4 + 3][lr] = va.w;
    float4 vb = *(const float4*)&B[(size_t)lr * 64 + k0 + lc * 4];
    Bs[lc * 4 + 0][lr] = vb.x; Bs[lc * 4 + 1][lr] = vb.y;
    Bs[lc * 4 + 2][lr] = vb.z; Bs[lc * 4 + 3][lr] = vb.w;
    __syncthreads();
#pragma unroll
    for (int k = 0; k < 16; k++) {
      float a[4], b[4];
      *(float4*)&a[0] = *(const float4*)&As[k][ty * 4];
      *(float4*)&b[0] = *(const float4*)&Bs[k][tx * 4];
#pragma unroll
      for (int i = 0; i < 4; i++)
#pragma unroll
        for (int j = 0; j < 4; j++) acc[i][j] += a[i] * b[j];
    }
    __syncthreads();
  }
#pragma unroll
  for (int i = 0; i < 4; i++) {
    int nt = m0 + ty * 4 + i;
#pragma unroll
    for (int j = 0; j < 4; j++) {
      int e = e0 + tx * 4 + j;
      dst[((size_t)nt * NHEAD + h) * EXP + e] = acc[i][j];
    }
  }
}

// ======================= warp-level top-k ====================================
__device__ __forceinline__ void warp_top16(float v[8], int lid, float& mv, int& mi) {
  for (int k = 0; k < KSEL; k++) {
    float bv = v[0];
    int br = 0;
#pragma unroll
    for (int r = 1; r < 8; r++)
      if (v[r] > bv) { bv = v[r]; br = r; }
    int code = br * 32 + lid;
#pragma unroll
    for (int off = 16; off; off >>= 1) {
      float ov = __shfl_xor_sync(0xffffffffu, bv, off);
      int oc = __shfl_xor_sync(0xffffffffu, code, off);
      if (ov > bv || (ov == bv && oc < code)) { bv = ov; code = oc; }
    }
    if (lid == k) { mv = bv; mi = code; }
    int owner = code & 31, reg = code >> 5;
    if (lid == owner) {
#pragma unroll
      for (int r = 0; r < 8; r++)
        if (r == reg) v[r] = -INFINITY;
    }
  }
}

__global__ __launch_bounds__(256) void topk_kernel() {
  int lid = threadIdx.x & 31;
  int w = threadIdx.x >> 5;
  int row = blockIdx.x * 8 + w;
  float v[8];
  float m1v = 0.f, m2v = 0.f, m3v = 0.f;
  int m1i = 0, m2i = 0, m3i = 0;

  const float* s1 = g_s1 + (size_t)row * EXP;
#pragma unroll
  for (int r = 0; r < 8; r++) v[r] = s1[r * 32 + lid];
  warp_top16(v, lid, m1v, m1i);

  const float* s2 = g_s2 + (size_t)row * EXP;
#pragma unroll
  for (int r = 0; r < 8; r++) v[r] = s2[r * 32 + lid];
  warp_top16(v, lid, m2v, m2i);

#pragma unroll
  for (int r = 0; r < 8; r++) {
    int t = r * 32 + lid;
    float a = __shfl_sync(0xffffffffu, m1v, t >> 4);
    float b = __shfl_sync(0xffffffffu, m2v, t & 15);
    v[r] = a + b;
  }
  warp_top16(v, lid, m3v, m3i);

  float mx = __shfl_sync(0xffffffffu, m3v, 0);
  float p = (lid < 16) ? expf(m3v - mx) : 0.f;
  float sum = p;
#pragma unroll
  for (int off = 16; off; off >>= 1) sum += __shfl_xor_sync(0xffffffffu, sum, off);
  float inv = 1.0f / sum;
  int i1 = __shfl_sync(0xffffffffu, m1i, (m3i >> 4) & 15);
  int i2 = __shfl_sync(0xffffffffu, m2i, m3i & 15);
  if (lid < 16) atomicAdd(&g_P[i1 * EXP + i2], p * inv);
}

// ======================= HMMA mainloop (r13 config: 256 thr, 2m x 4n) =========
#define BM 128
#define BN 128
#define SM_A 0
#define SM_B 16384
#define STAGE_BYTES 32768
#define NSTAGE 3
#define DSMEM_SZ (NSTAGE * STAGE_BYTES)

__device__ __forceinline__ uint32_t swz128(int row, int seg) {
  return (uint32_t)(row * 128 + ((seg ^ (row & 7)) << 4));
}

__device__ __forceinline__ void issue_chunk(
    uint32_t smb, int stage, const char* A, const char* B,
    size_t sA, size_t sB, int ck, int tid) {
  uint32_t base = smb + stage * STAGE_BYTES;
  size_t ko = (size_t)ck * 128;
#pragma unroll
  for (int t = 0; t < 4; t++) {
    int q = tid + t * 256;
    int row = q >> 3, seg = q & 7;
    cp16(base + SM_A + swz128(row, seg), A + (size_t)row * sA + ko + seg * 16);
  }
#pragma unroll
  for (int t = 0; t < 4; t++) {
    int q = tid + t * 256;
    int row = q >> 3, seg = q & 7;
    cp16(base + SM_B + swz128(row, seg), B + (size_t)row * sB + ko + seg * 16);
  }
  CP_COMMIT;
}

__device__ __forceinline__ void mainloop1(
    const char* A, const char* B, size_t sA, size_t sB, int NC,
    float acc[4][4][4], char* sm) {
  uint32_t smb = (uint32_t)__cvta_generic_to_shared(sm);
  int tid = threadIdx.x, lane = tid & 31, wid = tid >> 5;
  int wm = (wid & 1) * 64, wn = (wid >> 1) * 32;
  int arow = ((lane >> 3) & 1) * 8 + (lane & 7);
  int aseg = lane >> 4;

  issue_chunk(smb, 0, A, B, sA, sB, 0, tid);
  issue_chunk(smb, 1, A, B, sA, sB, 1, tid);

  for (int ck = 0; ck < NC; ck++) {
    if (ck == NC - 1) { CP_WAIT0; } else { CP_WAIT1; }
    __syncthreads();
    if (ck + 2 < NC)
      issue_chunk(smb, (ck + 2) % NSTAGE, A, B, sA, sB, ck + 2, tid);
    uint32_t base = smb + (ck % NSTAGE) * STAGE_BYTES;
#pragma unroll
    for (int s = 0; s < 4; s++) {
      int seg = s * 2 + aseg;
      uint32_t Af[4][4], Bf[2][4];
#pragma unroll
      for (int g = 0; g < 2; g++) {
        int row = wn + g * 16 + arow;
        ldsm4(Bf[g], base + SM_B + swz128(row, seg));
      }
#pragma unroll
      for (int mt = 0; mt < 4; mt++) {
        int row = wm + mt * 16 + arow;
        ldsm4(Af[mt], base + SM_A + swz128(row, seg));
      }
#pragma unroll
      for (int mt = 0; mt < 4; mt++)
#pragma unroll
        for (int nt = 0; nt < 4; nt++) {
          int g = nt >> 1, j = nt & 1;
          mma16816(acc[mt][nt], Af[mt], Bf[g][j], Bf[g][j + 2]);
        }
    }
  }
}

// ---------- D1: Sh = relu(Qh @ Wdh^T) * P ; M=1024, N=65536, K=512 -----------
__global__ __launch_bounds__(256, 2) void d1_kernel() {
  extern __shared__ __align__(1024) char dynsm[];
  int m0 = blockIdx.x * BM, n0 = blockIdx.y * BN;
  float acc[4][4][4];
#pragma unroll
  for (int a = 0; a < 4; a++)
#pragma unroll
    for (int c = 0; c < 4; c++)
#pragma unroll
      for (int d = 0; d < 4; d++) acc[a][c][d] = 0.f;

  mainloop1((const char*)(g_Qh + (size_t)m0 * 512),
            (const char*)(g_Wdh + (size_t)n0 * 512),
            1024, 1024, 8, acc, dynsm);

  int lane = threadIdx.x & 31, wid = threadIdx.x >> 5;
  int wm = (wid & 1) * 64, wn = (wid >> 1) * 32;
  int r0 = lane >> 2, cc = (lane & 3) * 2;
#pragma unroll
  for (int nt = 0; nt < 4; nt++) {
    int n = n0 + wn + nt * 8 + cc;
    float2 P2 = *(const float2*)&g_P[n];
#pragma unroll
    for (int mt = 0; mt < 4; mt++) {
#pragma unroll
      for (int h = 0; h < 2; h++) {
        int m = m0 + wm + mt * 16 + r0 + h * 8;
        float v0 = fmaxf(acc[mt][nt][2 * h + 0], 0.f) * P2.x;
        float v1 = fmaxf(acc[mt][nt][2 * h + 1], 0.f) * P2.y;
        *(uint32_t*)&g_Sh[(size_t)m * NE + n] = pack2h(v0, v1);
      }
    }
  }
}

// ---------- D2: out += Sh @ WuT^T ; M=1024, N=512, K=65536, splitK=9 ---------
__global__ __launch_bounds__(256, 2) void d2_kernel(float* __restrict__ out) {
  extern __shared__ __align__(1024) char dynsm[];
  int m0 = blockIdx.x * BM;
  int n0 = blockIdx.y * BN;
  int z = blockIdx.z;
  int start = z * 113 + (z < 7 ? z : 7);
  int cnt = 113 + (z < 7 ? 1 : 0);
  size_t kb = (size_t)start * 128;
  float acc[4][4][4];
#pragma unroll
  for (int a = 0; a < 4; a++)
#pragma unroll
    for (int c = 0; c < 4; c++)
#pragma unroll
      for (int d = 0; d < 4; d++) acc[a][c][d] = 0.f;

  mainloop1((const char*)g_Sh + (size_t)m0 * 131072 + kb,
            (const char*)g_WuTh + (size_t)n0 * 131072 + kb,
            131072, 131072, cnt, acc, dynsm);

  int lane = threadIdx.x & 31, wid = threadIdx.x >> 5;
  int wm = (wid & 1) * 64, wn = (wid >> 1) * 32;
  int r0 = lane >> 2, cc = (lane & 3) * 2;
#pragma unroll
  for (int nt = 0; nt < 4; nt++) {
    int n = n0 + wn + nt * 8 + cc;
#pragma unroll
    for (int mt = 0; mt < 4; mt++) {
#pragma unroll
      for (int h = 0; h < 2; h++) {
        int m = m0 + wm + mt * 16 + r0 + h * 8;
        atomicAdd(&out[(size_t)m * DIM + n], acc[mt][nt][2 * h + 0]);
        atomicAdd(&out[(size_t)m * DIM + n + 1], acc[mt][nt][2 * h + 1]);
      }
    }
  }
}

// ======================= launch ==============================================
extern "C" void kernel_launch(void* const* d_in, const int* in_sizes, int n_in,
                              void* d_out, int out_size) {
  const float* queries = (const float*)d_in[0];
  const float* Wq      = (const float*)d_in[1];
  const float* bq      = (const float*)d_in[2];
  const float* keys    = (const float*)d_in[3];
  const float* w_down  = (const float*)d_in[4];
  const float* w_up    = (const float*)d_in[5];
  float* out = (float*)d_out;

  cudaFuncSetAttribute(d1_kernel, cudaFuncAttributeMaxDynamicSharedMemorySize, DSMEM_SZ);
  cudaFuncSetAttribute(d2_kernel, cudaFuncAttributeMaxDynamicSharedMemorySize, DSMEM_SZ);

  prep_kernel<<<PREP_BLOCKS, 256>>>(out, queries, Wq, bq, w_down, w_up);
  scores_gemm_kernel<<<dim3(16, 4, 16), 256>>>(keys);
  topk_kernel<<<1024, 256>>>();
  d1_kernel<<<dim3(8, 512), 256, DSMEM_SZ>>>();
  d2_kernel<<<dim3(8, 4, 9), 256, DSMEM_SZ>>>(out);
}